// round 5
// baseline (speedup 1.0000x reference)
#include <cuda_runtime.h>
#include <cuda_bf16.h>
#include <cstdint>

// ---------------------------------------------------------------------------
// PointNet++ part-segmentation forward pass.
// prep -> FPS(4 levels, redux) -> knn20_all -> knn3_all -> SA x4 -> FP x4
//      -> seg head + transpose.
// MLP stages use packed fp32 FFMA2 (fma.rn.f32x2) with channel-major smem
// tiles so activation pairs come straight out of LDS.128 (broadcast).
// ---------------------------------------------------------------------------

#define B_ 8
#define N_ 4096

// ---- scratch layout (floats) ----
#define SZ_XYZ4  (B_*N_*4)
#define SZ_NRM   (B_*N_*3)
#define SZ_SKIP0 (B_*N_*22)
#define SZ_X1    (B_*512*4)
#define SZ_X2    (B_*256*4)
#define SZ_X3    (B_*128*4)
#define SZ_X4    (B_*64*4)
#define SZ_F1    (B_*512*64)
#define SZ_F2    (B_*256*128)
#define SZ_F3    (B_*128*256)
#define SZ_F4    (B_*64*512)
#define SZ_G3    (B_*128*512)
#define SZ_G2    (B_*256*256)
#define SZ_G1    (B_*512*128)
#define SZ_G0    (B_*N_*128)
#define SZ_NI1   (B_*512*20)
#define SZ_NI2   (B_*256*20)
#define SZ_NI3   (B_*128*20)
#define SZ_NI4   (B_*64*20)
#define SZ_I33   (B_*128*3)
#define SZ_I32   (B_*256*3)
#define SZ_I31   (B_*512*3)
#define SZ_I30   (B_*N_*3)

#define OFF_XYZ4  0
#define OFF_NRM   (OFF_XYZ4 + SZ_XYZ4)
#define OFF_SKIP0 (OFF_NRM + SZ_NRM)
#define OFF_X1    (OFF_SKIP0 + SZ_SKIP0)
#define OFF_X2    (OFF_X1 + SZ_X1)
#define OFF_X3    (OFF_X2 + SZ_X2)
#define OFF_X4    (OFF_X3 + SZ_X3)
#define OFF_F1    (OFF_X4 + SZ_X4)
#define OFF_F2    (OFF_F1 + SZ_F1)
#define OFF_F3    (OFF_F2 + SZ_F2)
#define OFF_F4    (OFF_F3 + SZ_F3)
#define OFF_G3    (OFF_F4 + SZ_F4)
#define OFF_G2    (OFF_G3 + SZ_G3)
#define OFF_G1    (OFF_G2 + SZ_G2)
#define OFF_G0    (OFF_G1 + SZ_G1)
#define OFF_NI1   (OFF_G0 + SZ_G0)
#define OFF_NI2   (OFF_NI1 + SZ_NI1)
#define OFF_NI3   (OFF_NI2 + SZ_NI2)
#define OFF_NI4   (OFF_NI3 + SZ_NI3)
#define OFF_I33   (OFF_NI4 + SZ_NI4)
#define OFF_I32   (OFF_I33 + SZ_I33)
#define OFF_I31   (OFF_I32 + SZ_I32)
#define OFF_I30   (OFF_I31 + SZ_I31)
#define SCRATCH_TOTAL (OFF_I30 + SZ_I30)

__device__ __align__(16) float g_scratch[SCRATCH_TOTAL];

// ---- packed fp32 helpers ----
typedef unsigned long long u64;
__device__ __forceinline__ u64 pk2(float lo, float hi) {
    u64 r; asm("mov.b64 %0, {%1, %2};" : "=l"(r) : "f"(lo), "f"(hi)); return r;
}
__device__ __forceinline__ void upk2(float& lo, float& hi, u64 v) {
    asm("mov.b64 {%0, %1}, %2;" : "=f"(lo), "=f"(hi) : "l"(v));
}
__device__ __forceinline__ void ffma2(u64& acc, u64 a, u64 b) {
    asm("fma.rn.f32x2 %0, %1, %2, %0;" : "+l"(acc) : "l"(a), "l"(b));
}

// ---------------------------------------------------------------------------
// prep
// ---------------------------------------------------------------------------
__global__ void prep_kernel(const float* __restrict__ x, const float* __restrict__ cls,
                            float4* __restrict__ xyz4, float* __restrict__ nrm,
                            float* __restrict__ skip0) {
    int n = blockIdx.x * blockDim.x + threadIdx.x;
    int b = blockIdx.y;
    if (n >= N_) return;
    const float* xb = x + (size_t)b * 6 * N_;
    float px = xb[0*N_+n], py = xb[1*N_+n], pz = xb[2*N_+n];
    float nx = xb[3*N_+n], ny = xb[4*N_+n], nz = xb[5*N_+n];
    float pp = px*px + py*py + pz*pz;
    xyz4[(size_t)b*N_+n] = make_float4(px, py, pz, pp);
    float* np_ = nrm + ((size_t)b*N_+n)*3;
    np_[0]=nx; np_[1]=ny; np_[2]=nz;
    float* sk = skip0 + ((size_t)b*N_+n)*22;
    #pragma unroll
    for (int c = 0; c < 16; c++) sk[c] = cls[b*16+c];
    sk[16]=px; sk[17]=py; sk[18]=pz;
    sk[19]=nx; sk[20]=ny; sk[21]=nz;
}

// ---------------------------------------------------------------------------
// FPS (unchanged from R3): register-resident dists, smem cache, REDUX argmax.
// ---------------------------------------------------------------------------
#define FPS_NT 512

struct FpsRed {
    unsigned key[16];
    int      idx[16];
    float4   bc;
};

template<int P>
__device__ void fps_level(const float4* __restrict__ pts, int M, int S,
                          float4* __restrict__ o, float4* spts, FpsRed* r) {
    const int tid = threadIdx.x;
    float px[P], py[P], pz[P], dist[P];
    #pragma unroll
    for (int j = 0; j < P; j++) {
        int i = tid + j*FPS_NT;
        if (i < M) {
            float4 p = pts[i];
            spts[i] = p;
            px[j]=p.x; py[j]=p.y; pz[j]=p.z; dist[j]=1e10f;
        } else {
            px[j]=0.f; py[j]=0.f; pz[j]=0.f; dist[j]=-1.0f;
        }
    }
    if (tid == 0) {
        float4 p0 = pts[0];
        r->bc = make_float4(p0.x, p0.y, p0.z, p0.x*p0.x + p0.y*p0.y + p0.z*p0.z);
    }
    __syncthreads();

    for (int it = 0; it < S; ++it) {
        float4 f = r->bc;
        if (tid == 0) o[it] = f;

        float bv = -1.0f; int bj = 0;
        #pragma unroll
        for (int j = 0; j < P; j++) {
            float dx = px[j]-f.x, dy = py[j]-f.y, dz = pz[j]-f.z;
            float d = dx*dx + dy*dy + dz*dz;
            float nd = fminf(dist[j], d);
            dist[j] = nd;
            if (nd > bv) { bv = nd; bj = j; }
        }
        int myi = tid + bj*FPS_NT;
        unsigned key = (bv > 0.0f) ? __float_as_uint(bv) : 0u;
        unsigned wmax = __reduce_max_sync(0xffffffffu, key);
        int cand = (key == wmax) ? myi : 0x7fffffff;
        int wmin = __reduce_min_sync(0xffffffffu, cand);
        if ((tid & 31) == 0) { r->key[tid>>5] = wmax; r->idx[tid>>5] = wmin; }
        __syncthreads();
        if (tid < 32) {
            unsigned k2 = (tid < (FPS_NT/32)) ? r->key[tid] : 0u;
            int      i2 = (tid < (FPS_NT/32)) ? r->idx[tid] : 0x7fffffff;
            unsigned g  = __reduce_max_sync(0xffffffffu, k2);
            int c2 = (k2 == g) ? i2 : 0x7fffffff;
            int win = __reduce_min_sync(0xffffffffu, c2);
            if (tid == 0) {
                float4 p = spts[win];
                r->bc = make_float4(p.x, p.y, p.z, p.x*p.x + p.y*p.y + p.z*p.z);
            }
        }
        __syncthreads();
    }
    __syncthreads();
}

__global__ void __launch_bounds__(FPS_NT)
fps_all_kernel(const float4* __restrict__ xyz4,
               float4* __restrict__ x1, float4* __restrict__ x2,
               float4* __restrict__ x3, float4* __restrict__ x4) {
    extern __shared__ __align__(16) float4 spts[];
    __shared__ FpsRed r;
    int b = blockIdx.x;
    fps_level<8>(xyz4 + (size_t)b*N_, N_, 512, x1 + (size_t)b*512, spts, &r);
    fps_level<1>(x1 + (size_t)b*512, 512, 256, x2 + (size_t)b*256, spts, &r);
    fps_level<1>(x2 + (size_t)b*256, 256, 128, x3 + (size_t)b*128, spts, &r);
    fps_level<1>(x3 + (size_t)b*128, 128, 64,  x4 + (size_t)b*64,  spts, &r);
}

// ---------------------------------------------------------------------------
// kNN body (expanded distance, smallest-index tie-break like top_k).
// ---------------------------------------------------------------------------
template<int K>
__device__ __forceinline__ void knn_body(const float4* __restrict__ q,
                                         const float4* __restrict__ ref,
                                         int s, int M, int* __restrict__ out) {
    float4 qp = q[s];
    float qq = qp.w;
    float bd[K]; int bi[K];
    #pragma unroll
    for (int j = 0; j < K; j++) { bd[j] = 3.0e38f; bi[j] = 0; }
    for (int m = 0; m < M; m++) {
        float4 r = ref[m];
        float d = qq - 2.0f*(qp.x*r.x + qp.y*r.y + qp.z*r.z) + r.w;
        if (d < bd[K-1]) {
            #pragma unroll
            for (int t = K-1; t >= 0; --t) {
                bool pred_gt = (t > 0) ? (bd[t-1] > d) : false;
                if (bd[t] > d) {
                    if (pred_gt) { bd[t] = bd[t-1]; bi[t] = bi[t-1]; }
                    else         { bd[t] = d;       bi[t] = m; }
                }
            }
        }
    }
    int* o = out + (size_t)s*K;
    #pragma unroll
    for (int j = 0; j < K; j++) o[j] = bi[j];
}

__global__ void knn20_all_kernel(const float4* __restrict__ xyz4,
                                 const float4* __restrict__ x1, const float4* __restrict__ x2,
                                 const float4* __restrict__ x3, const float4* __restrict__ x4,
                                 int* __restrict__ ni1, int* __restrict__ ni2,
                                 int* __restrict__ ni3, int* __restrict__ ni4) {
    int blk = blockIdx.x, b = blockIdx.y, tid = threadIdx.x;
    if (blk < 4) {
        int s = blk*128 + tid;
        knn_body<20>(x1 + (size_t)b*512, xyz4 + (size_t)b*N_, s, N_, ni1 + (size_t)b*512*20);
    } else if (blk < 6) {
        int s = (blk-4)*128 + tid;
        knn_body<20>(x2 + (size_t)b*256, x1 + (size_t)b*512, s, 512, ni2 + (size_t)b*256*20);
    } else if (blk < 7) {
        int s = tid;
        knn_body<20>(x3 + (size_t)b*128, x2 + (size_t)b*256, s, 256, ni3 + (size_t)b*128*20);
    } else {
        if (tid < 64)
            knn_body<20>(x4 + (size_t)b*64, x3 + (size_t)b*128, tid, 128, ni4 + (size_t)b*64*20);
    }
}

__global__ void knn3_all_kernel(const float4* __restrict__ xyz4,
                                const float4* __restrict__ x1, const float4* __restrict__ x2,
                                const float4* __restrict__ x3, const float4* __restrict__ x4,
                                int* __restrict__ i30, int* __restrict__ i31,
                                int* __restrict__ i32, int* __restrict__ i33) {
    int blk = blockIdx.x, b = blockIdx.y, tid = threadIdx.x;
    if (blk < 32) {
        int s = blk*128 + tid;
        knn_body<3>(xyz4 + (size_t)b*N_, x1 + (size_t)b*512, s, 512, i30 + (size_t)b*N_*3);
    } else if (blk < 36) {
        int s = (blk-32)*128 + tid;
        knn_body<3>(x1 + (size_t)b*512, x2 + (size_t)b*256, s, 256, i31 + (size_t)b*512*3);
    } else if (blk < 38) {
        int s = (blk-36)*128 + tid;
        knn_body<3>(x2 + (size_t)b*256, x3 + (size_t)b*128, s, 128, i32 + (size_t)b*256*3);
    } else {
        knn_body<3>(x3 + (size_t)b*128, x4 + (size_t)b*64, tid, 64, i33 + (size_t)b*128*3);
    }
}

// ---------------------------------------------------------------------------
// SA block: gather-group -> MLP (FFMA2) -> relu -> max over K=20.
// Shared tile channel-major sg[c][k]: LDS.128 yields 2 packed (k,k+1) pairs.
// ---------------------------------------------------------------------------
template<int CIN, int COUT>
__global__ void sa_kernel(const float4* __restrict__ qxyz, const float4* __restrict__ rxyz,
                          const float* __restrict__ rfeat, const int* __restrict__ nidx,
                          const float* __restrict__ W, const float* __restrict__ bias,
                          int S, int M, float* __restrict__ out) {
    constexpr int K = 20;           // 80 bytes per row: 16B-aligned rows
    constexpr int KH = K/2;         // 10 packed accumulators
    constexpr int CFEAT = CIN - 3;
    __shared__ __align__(16) float sg[CIN * K];
    int s = blockIdx.x, b = blockIdx.y;
    const int* ni = nidx + ((size_t)b*S + s)*K;
    float4 qc = qxyz[(size_t)b*S + s];
    int tid = threadIdx.x;

    for (int e = tid; e < K*CIN; e += COUT) {
        int k = e / CIN, c = e - k*CIN;
        int n = ni[k];
        float v;
        if (c < 3) {
            float ctr = (c == 0) ? qc.x : (c == 1) ? qc.y : qc.z;
            v = ((const float*)(rxyz + (size_t)b*M + n))[c] - ctr;
        } else {
            v = rfeat[((size_t)b*M + n)*CFEAT + (c-3)];
        }
        sg[c*K + k] = v;
    }
    __syncthreads();

    int d = tid;
    float bb = bias[d];
    u64 acc2[KH];
    u64 binit = pk2(bb, bb);
    #pragma unroll
    for (int p = 0; p < KH; p++) acc2[p] = binit;

    #pragma unroll 4
    for (int c = 0; c < CIN; c++) {
        float w = W[c*COUT + d];
        u64 w2 = pk2(w, w);
        const float* row = &sg[c*K];
        #pragma unroll
        for (int q = 0; q < K/4; q++) {
            ulonglong2 v = *(const ulonglong2*)&row[q*4];
            ffma2(acc2[2*q+0], v.x, w2);
            ffma2(acc2[2*q+1], v.y, w2);
        }
    }
    float m = -3.0e38f;
    #pragma unroll
    for (int p = 0; p < KH; p++) {
        float lo, hi; upk2(lo, hi, acc2[p]);
        m = fmaxf(m, fmaxf(lo, hi));
    }
    out[((size_t)b*S + s)*COUT + d] = fmaxf(m, 0.0f);
}

// ---------------------------------------------------------------------------
// FP block: 3-NN interp -> concat skip -> MLP (FFMA2) -> relu.
// Shared tile channel-major cat[c][t]: LDS.128 -> 2 packed (t,t+1) pairs.
// ---------------------------------------------------------------------------
template<int CI, int CS, int COUT, int TS>
__global__ void fp_kernel(const float4* __restrict__ xq, const float4* __restrict__ xr,
                          const float* __restrict__ fr, const float* __restrict__ skip,
                          const int* __restrict__ idx3,
                          const float* __restrict__ W, const float* __restrict__ bias,
                          int Sq, int M, float* __restrict__ out) {
    constexpr int CTOT = CI + CS;
    constexpr int TH = TS/2;
    __shared__ __align__(16) float cat[CTOT * TS];
    __shared__ float sw[TS][3];
    __shared__ int   si[TS][3];
    int b = blockIdx.y;
    int s0 = blockIdx.x * TS;
    int tid = threadIdx.x;

    if (tid < TS) {
        int s = s0 + tid;
        const int* ip = idx3 + ((size_t)b*Sq + s)*3;
        float4 qp = xq[(size_t)b*Sq + s];
        float wv[3]; int ii[3]; float wsum = 0.0f;
        #pragma unroll
        for (int j = 0; j < 3; j++) {
            int i = ip[j]; ii[j] = i;
            float4 r = xr[(size_t)b*M + i];
            float dx = r.x-qp.x, dy = r.y-qp.y, dz = r.z-qp.z;
            float dd = dx*dx + dy*dy + dz*dz;
            float w = 1.0f / (dd + 1e-8f);
            wv[j] = w; wsum += w;
        }
        float inv = 1.0f / wsum;
        #pragma unroll
        for (int j = 0; j < 3; j++) { sw[tid][j] = wv[j]*inv; si[tid][j] = ii[j]; }
    }
    __syncthreads();

    for (int e = tid; e < TS*CI; e += COUT) {
        int t = e / CI, c = e - t*CI;     // CI is a power of two in all uses
        size_t base = (size_t)b*M;
        float v = sw[t][0]*fr[(base + si[t][0])*CI + c]
                + sw[t][1]*fr[(base + si[t][1])*CI + c]
                + sw[t][2]*fr[(base + si[t][2])*CI + c];
        cat[c*TS + t] = v;
    }
    for (int e = tid; e < TS*CS; e += COUT) {
        int t = e / CS, c = e - t*CS;
        cat[(CI + c)*TS + t] = skip[((size_t)b*Sq + s0 + t)*CS + c];
    }
    __syncthreads();

    int d = tid;
    float bb = bias[d];
    u64 acc2[TH];
    u64 binit = pk2(bb, bb);
    #pragma unroll
    for (int p = 0; p < TH; p++) acc2[p] = binit;

    #pragma unroll 4
    for (int c = 0; c < CTOT; c++) {
        float w = W[c*COUT + d];
        u64 w2 = pk2(w, w);
        const float* row = &cat[c*TS];
        #pragma unroll
        for (int q = 0; q < TS/4; q++) {
            ulonglong2 v = *(const ulonglong2*)&row[q*4];
            ffma2(acc2[2*q+0], v.x, w2);
            ffma2(acc2[2*q+1], v.y, w2);
        }
    }
    float* ob = out + ((size_t)b*Sq + s0)*COUT + d;
    #pragma unroll
    for (int p = 0; p < TH; p++) {
        float lo, hi; upk2(lo, hi, acc2[p]);
        ob[(size_t)(2*p+0)*COUT] = fmaxf(lo, 0.0f);
        ob[(size_t)(2*p+1)*COUT] = fmaxf(hi, 0.0f);
    }
}

// ---------------------------------------------------------------------------
// Seg head (FFMA2, channel-major tile)
// ---------------------------------------------------------------------------
__global__ void seg_kernel(const float* __restrict__ g0, const float* __restrict__ Wseg,
                           const float* __restrict__ bseg, float* __restrict__ out) {
    constexpr int TS = 16;
    constexpr int TH = TS/2;
    __shared__ __align__(16) float sg[128 * TS];   // [c][t]
    int b = blockIdx.y;
    int s0 = blockIdx.x * TS;
    int tid = threadIdx.x; // 64
    for (int e = tid; e < TS*128; e += 64) {
        int t = e >> 7, c = e & 127;
        sg[c*TS + t] = g0[((size_t)b*N_ + s0 + t)*128 + c];
    }
    __syncthreads();
    int j = tid;
    if (j < 50) {
        u64 acc2[TH];
        #pragma unroll
        for (int p = 0; p < TH; p++) acc2[p] = 0ull;
        #pragma unroll 4
        for (int c = 0; c < 128; c++) {
            float w = Wseg[c*50 + j];
            u64 w2 = pk2(w, w);
            const float* row = &sg[c*TS];
            #pragma unroll
            for (int q = 0; q < TS/4; q++) {
                ulonglong2 v = *(const ulonglong2*)&row[q*4];
                ffma2(acc2[2*q+0], v.x, w2);
                ffma2(acc2[2*q+1], v.y, w2);
            }
        }
        float bb = bseg[j];
        #pragma unroll
        for (int p = 0; p < TH; p++) {
            float lo, hi; upk2(lo, hi, acc2[p]);
            out[((size_t)b*N_ + s0 + 2*p+0)*50 + j] = lo + bb;
            out[((size_t)b*N_ + s0 + 2*p+1)*50 + j] = hi + bb;
        }
    }
}

// ---------------------------------------------------------------------------
// Transpose g0 [B,N,128] -> [B,128,N]
// ---------------------------------------------------------------------------
__global__ void transpose_kernel(const float* __restrict__ g0, float* __restrict__ out) {
    __shared__ float tile[32][33];
    int b = blockIdx.z;
    int n0 = blockIdx.x * 32, c0 = blockIdx.y * 32;
    int tx = threadIdx.x, ty = threadIdx.y;
    tile[ty][tx] = g0[((size_t)b*N_ + n0 + ty)*128 + c0 + tx];
    __syncthreads();
    out[((size_t)b*128 + c0 + ty)*N_ + n0 + tx] = tile[tx][ty];
}

// ---------------------------------------------------------------------------
extern "C" void kernel_launch(void* const* d_in, const int* in_sizes, int n_in,
                              void* d_out, int out_size) {
    const float* x      = (const float*)d_in[0];
    const float* cls    = (const float*)d_in[1];
    const float* W0 = (const float*)d_in[2];  const float* b0 = (const float*)d_in[3];
    const float* W1 = (const float*)d_in[4];  const float* b1 = (const float*)d_in[5];
    const float* W2 = (const float*)d_in[6];  const float* b2 = (const float*)d_in[7];
    const float* W3 = (const float*)d_in[8];  const float* b3 = (const float*)d_in[9];
    const float* F3 = (const float*)d_in[10]; const float* fb3 = (const float*)d_in[11];
    const float* F2 = (const float*)d_in[12]; const float* fb2 = (const float*)d_in[13];
    const float* F1 = (const float*)d_in[14]; const float* fb1 = (const float*)d_in[15];
    const float* F0 = (const float*)d_in[16]; const float* fb0 = (const float*)d_in[17];
    const float* Wseg = (const float*)d_in[18]; const float* bseg = (const float*)d_in[19];

    float* scratch = nullptr;
    cudaGetSymbolAddress((void**)&scratch, g_scratch);

    float4* xyz4 = (float4*)(scratch + OFF_XYZ4);
    float* nrm   = scratch + OFF_NRM;
    float* skip0 = scratch + OFF_SKIP0;
    float4* x1 = (float4*)(scratch + OFF_X1);
    float4* x2 = (float4*)(scratch + OFF_X2);
    float4* x3 = (float4*)(scratch + OFF_X3);
    float4* x4 = (float4*)(scratch + OFF_X4);
    float* f1 = scratch + OFF_F1;  float* f2 = scratch + OFF_F2;
    float* f3 = scratch + OFF_F3;  float* f4 = scratch + OFF_F4;
    float* g3 = scratch + OFF_G3;  float* g2 = scratch + OFF_G2;
    float* g1 = scratch + OFF_G1;  float* g0 = scratch + OFF_G0;
    int* ni1 = (int*)(scratch + OFF_NI1);
    int* ni2 = (int*)(scratch + OFF_NI2);
    int* ni3 = (int*)(scratch + OFF_NI3);
    int* ni4 = (int*)(scratch + OFF_NI4);
    int* i33 = (int*)(scratch + OFF_I33);
    int* i32 = (int*)(scratch + OFF_I32);
    int* i31 = (int*)(scratch + OFF_I31);
    int* i30 = (int*)(scratch + OFF_I30);

    float* out1 = (float*)d_out;                    // result [B,N,50]
    float* out2 = out1 + (size_t)B_ * N_ * 50;      // g0^T   [B,128,N]

    const int fps_smem = N_ * (int)sizeof(float4);  // 64 KB point cache
    cudaFuncSetAttribute(fps_all_kernel, cudaFuncAttributeMaxDynamicSharedMemorySize, fps_smem);

    prep_kernel<<<dim3(N_/256, B_), 256>>>(x, cls, xyz4, nrm, skip0);
    fps_all_kernel<<<B_, FPS_NT, fps_smem>>>(xyz4, x1, x2, x3, x4);

    knn20_all_kernel<<<dim3(8, B_), 128>>>(xyz4, x1, x2, x3, x4, ni1, ni2, ni3, ni4);
    knn3_all_kernel<<<dim3(39, B_), 128>>>(xyz4, x1, x2, x3, x4, i30, i31, i32, i33);

    // SA chain
    sa_kernel<6,64><<<dim3(512, B_), 64>>>(x1, xyz4, nrm, ni1, W0, b0, 512, N_, f1);
    sa_kernel<67,128><<<dim3(256, B_), 128>>>(x2, x1, f1, ni2, W1, b1, 256, 512, f2);
    sa_kernel<131,256><<<dim3(128, B_), 256>>>(x3, x2, f2, ni3, W2, b2, 128, 256, f3);
    sa_kernel<259,512><<<dim3(64, B_), 512>>>(x4, x3, f3, ni4, W3, b3, 64, 128, f4);

    // FP chain (TS=8 for small grids, TS=16 for large)
    fp_kernel<512,256,512,8><<<dim3(128/8, B_), 512>>>(x3, x4, f4, f3, i33, F3, fb3, 128, 64, g3);
    fp_kernel<512,128,256,8><<<dim3(256/8, B_), 256>>>(x2, x3, g3, f2, i32, F2, fb2, 256, 128, g2);
    fp_kernel<256,64,128,16><<<dim3(512/16, B_), 128>>>(x1, x2, g2, f1, i31, F1, fb1, 512, 256, g1);
    fp_kernel<128,22,128,16><<<dim3(N_/16, B_), 128>>>(xyz4, x1, g1, skip0, i30, F0, fb0, N_, 512, g0);

    // Seg head + transposed feature output
    seg_kernel<<<dim3(N_/16, B_), 64>>>(g0, Wseg, bseg, out1);
    transpose_kernel<<<dim3(N_/32, 128/32, B_), dim3(32,32)>>>(g0, out2);
}

// round 6
// speedup vs baseline: 1.9148x; 1.9148x over previous
#include <cuda_runtime.h>
#include <cuda_bf16.h>
#include <cstdint>

// ---------------------------------------------------------------------------
// PointNet++ part-segmentation forward pass.
// prep -> FPS(4 levels, redux) -> knn20_all -> knn3_all -> SA x4 -> FP x4
//      -> seg head + transpose.
// Coordinates stored as float4 (x,y,z,|p|^2). kNN ref loops unrolled x4.
// ---------------------------------------------------------------------------

#define B_ 8
#define N_ 4096

// ---- scratch layout (floats) ----
#define SZ_XYZ4  (B_*N_*4)
#define SZ_NRM   (B_*N_*3)
#define SZ_SKIP0 (B_*N_*22)
#define SZ_X1    (B_*512*4)
#define SZ_X2    (B_*256*4)
#define SZ_X3    (B_*128*4)
#define SZ_X4    (B_*64*4)
#define SZ_F1    (B_*512*64)
#define SZ_F2    (B_*256*128)
#define SZ_F3    (B_*128*256)
#define SZ_F4    (B_*64*512)
#define SZ_G3    (B_*128*512)
#define SZ_G2    (B_*256*256)
#define SZ_G1    (B_*512*128)
#define SZ_G0    (B_*N_*128)
#define SZ_NI1   (B_*512*20)
#define SZ_NI2   (B_*256*20)
#define SZ_NI3   (B_*128*20)
#define SZ_NI4   (B_*64*20)
#define SZ_I33   (B_*128*3)
#define SZ_I32   (B_*256*3)
#define SZ_I31   (B_*512*3)
#define SZ_I30   (B_*N_*3)

#define OFF_XYZ4  0
#define OFF_NRM   (OFF_XYZ4 + SZ_XYZ4)
#define OFF_SKIP0 (OFF_NRM + SZ_NRM)
#define OFF_X1    (OFF_SKIP0 + SZ_SKIP0)
#define OFF_X2    (OFF_X1 + SZ_X1)
#define OFF_X3    (OFF_X2 + SZ_X2)
#define OFF_X4    (OFF_X3 + SZ_X3)
#define OFF_F1    (OFF_X4 + SZ_X4)
#define OFF_F2    (OFF_F1 + SZ_F1)
#define OFF_F3    (OFF_F2 + SZ_F2)
#define OFF_F4    (OFF_F3 + SZ_F3)
#define OFF_G3    (OFF_F4 + SZ_F4)
#define OFF_G2    (OFF_G3 + SZ_G3)
#define OFF_G1    (OFF_G2 + SZ_G2)
#define OFF_G0    (OFF_G1 + SZ_G1)
#define OFF_NI1   (OFF_G0 + SZ_G0)
#define OFF_NI2   (OFF_NI1 + SZ_NI1)
#define OFF_NI3   (OFF_NI2 + SZ_NI2)
#define OFF_NI4   (OFF_NI3 + SZ_NI3)
#define OFF_I33   (OFF_NI4 + SZ_NI4)
#define OFF_I32   (OFF_I33 + SZ_I33)
#define OFF_I31   (OFF_I32 + SZ_I32)
#define OFF_I30   (OFF_I31 + SZ_I31)
#define SCRATCH_TOTAL (OFF_I30 + SZ_I30)

__device__ __align__(16) float g_scratch[SCRATCH_TOTAL];

// ---------------------------------------------------------------------------
// prep
// ---------------------------------------------------------------------------
__global__ void prep_kernel(const float* __restrict__ x, const float* __restrict__ cls,
                            float4* __restrict__ xyz4, float* __restrict__ nrm,
                            float* __restrict__ skip0) {
    int n = blockIdx.x * blockDim.x + threadIdx.x;
    int b = blockIdx.y;
    if (n >= N_) return;
    const float* xb = x + (size_t)b * 6 * N_;
    float px = xb[0*N_+n], py = xb[1*N_+n], pz = xb[2*N_+n];
    float nx = xb[3*N_+n], ny = xb[4*N_+n], nz = xb[5*N_+n];
    float pp = px*px + py*py + pz*pz;
    xyz4[(size_t)b*N_+n] = make_float4(px, py, pz, pp);
    float* np_ = nrm + ((size_t)b*N_+n)*3;
    np_[0]=nx; np_[1]=ny; np_[2]=nz;
    float* sk = skip0 + ((size_t)b*N_+n)*22;
    #pragma unroll
    for (int c = 0; c < 16; c++) sk[c] = cls[b*16+c];
    sk[16]=px; sk[17]=py; sk[18]=pz;
    sk[19]=nx; sk[20]=ny; sk[21]=nz;
}

// ---------------------------------------------------------------------------
// FPS: register-resident dists, smem point cache, REDUX-based argmax.
// Tie-break: max dist, then smallest index (matches jnp.argmax / scan order).
// ---------------------------------------------------------------------------
#define FPS_NT 512

struct FpsRed {
    unsigned key[16];
    int      idx[16];
    float4   bc;
};

template<int P>
__device__ void fps_level(const float4* __restrict__ pts, int M, int S,
                          float4* __restrict__ o, float4* spts, FpsRed* r) {
    const int tid = threadIdx.x;
    float px[P], py[P], pz[P], dist[P];
    #pragma unroll
    for (int j = 0; j < P; j++) {
        int i = tid + j*FPS_NT;
        if (i < M) {
            float4 p = pts[i];
            spts[i] = p;
            px[j]=p.x; py[j]=p.y; pz[j]=p.z; dist[j]=1e10f;
        } else {
            px[j]=0.f; py[j]=0.f; pz[j]=0.f; dist[j]=-1.0f;
        }
    }
    if (tid == 0) {
        float4 p0 = pts[0];
        r->bc = make_float4(p0.x, p0.y, p0.z, p0.x*p0.x + p0.y*p0.y + p0.z*p0.z);
    }
    __syncthreads();

    for (int it = 0; it < S; ++it) {
        float4 f = r->bc;
        if (tid == 0) o[it] = f;

        float bv = -1.0f; int bj = 0;
        #pragma unroll
        for (int j = 0; j < P; j++) {
            float dx = px[j]-f.x, dy = py[j]-f.y, dz = pz[j]-f.z;
            float d = dx*dx + dy*dy + dz*dz;
            float nd = fminf(dist[j], d);
            dist[j] = nd;
            if (nd > bv) { bv = nd; bj = j; }
        }
        int myi = tid + bj*FPS_NT;
        unsigned key = (bv > 0.0f) ? __float_as_uint(bv) : 0u;
        unsigned wmax = __reduce_max_sync(0xffffffffu, key);
        int cand = (key == wmax) ? myi : 0x7fffffff;
        int wmin = __reduce_min_sync(0xffffffffu, cand);
        if ((tid & 31) == 0) { r->key[tid>>5] = wmax; r->idx[tid>>5] = wmin; }
        __syncthreads();
        if (tid < 32) {
            unsigned k2 = (tid < (FPS_NT/32)) ? r->key[tid] : 0u;
            int      i2 = (tid < (FPS_NT/32)) ? r->idx[tid] : 0x7fffffff;
            unsigned g  = __reduce_max_sync(0xffffffffu, k2);
            int c2 = (k2 == g) ? i2 : 0x7fffffff;
            int win = __reduce_min_sync(0xffffffffu, c2);
            if (tid == 0) {
                float4 p = spts[win];
                r->bc = make_float4(p.x, p.y, p.z, p.x*p.x + p.y*p.y + p.z*p.z);
            }
        }
        __syncthreads();
    }
    __syncthreads();
}

__global__ void __launch_bounds__(FPS_NT)
fps_all_kernel(const float4* __restrict__ xyz4,
               float4* __restrict__ x1, float4* __restrict__ x2,
               float4* __restrict__ x3, float4* __restrict__ x4) {
    extern __shared__ __align__(16) float4 spts[];
    __shared__ FpsRed r;
    int b = blockIdx.x;
    fps_level<8>(xyz4 + (size_t)b*N_, N_, 512, x1 + (size_t)b*512, spts, &r);
    fps_level<1>(x1 + (size_t)b*512, 512, 256, x2 + (size_t)b*256, spts, &r);
    fps_level<1>(x2 + (size_t)b*256, 256, 128, x3 + (size_t)b*128, spts, &r);
    fps_level<1>(x3 + (size_t)b*128, 128, 64,  x4 + (size_t)b*64,  spts, &r);
}

// ---------------------------------------------------------------------------
// kNN body, ref loop unrolled x4 for MLP=4 (M always divisible by 4).
// Insert checks stay in ascending-m order: tie-break identical to top_k.
// ---------------------------------------------------------------------------
template<int K>
__device__ __forceinline__ void knn_insert(float d, int m, float* bd, int* bi) {
    if (d < bd[K-1]) {
        #pragma unroll
        for (int t = K-1; t >= 0; --t) {
            bool pred_gt = (t > 0) ? (bd[t-1] > d) : false;
            if (bd[t] > d) {
                if (pred_gt) { bd[t] = bd[t-1]; bi[t] = bi[t-1]; }
                else         { bd[t] = d;       bi[t] = m; }
            }
        }
    }
}

template<int K>
__device__ __forceinline__ void knn_body(const float4* __restrict__ q,
                                         const float4* __restrict__ ref,
                                         int s, int M, int* __restrict__ out) {
    float4 qp = q[s];
    float qq = qp.w;
    float bd[K]; int bi[K];
    #pragma unroll
    for (int j = 0; j < K; j++) { bd[j] = 3.0e38f; bi[j] = 0; }
    for (int m = 0; m < M; m += 4) {
        float4 r0 = ref[m+0];
        float4 r1 = ref[m+1];
        float4 r2 = ref[m+2];
        float4 r3 = ref[m+3];
        float d0 = qq - 2.0f*(qp.x*r0.x + qp.y*r0.y + qp.z*r0.z) + r0.w;
        float d1 = qq - 2.0f*(qp.x*r1.x + qp.y*r1.y + qp.z*r1.z) + r1.w;
        float d2 = qq - 2.0f*(qp.x*r2.x + qp.y*r2.y + qp.z*r2.z) + r2.w;
        float d3 = qq - 2.0f*(qp.x*r3.x + qp.y*r3.y + qp.z*r3.z) + r3.w;
        knn_insert<K>(d0, m+0, bd, bi);
        knn_insert<K>(d1, m+1, bd, bi);
        knn_insert<K>(d2, m+2, bd, bi);
        knn_insert<K>(d3, m+3, bd, bi);
    }
    int* o = out + (size_t)s*K;
    #pragma unroll
    for (int j = 0; j < K; j++) o[j] = bi[j];
}

__global__ void knn20_all_kernel(const float4* __restrict__ xyz4,
                                 const float4* __restrict__ x1, const float4* __restrict__ x2,
                                 const float4* __restrict__ x3, const float4* __restrict__ x4,
                                 int* __restrict__ ni1, int* __restrict__ ni2,
                                 int* __restrict__ ni3, int* __restrict__ ni4) {
    int blk = blockIdx.x, b = blockIdx.y, tid = threadIdx.x;
    if (blk < 4) {
        int s = blk*128 + tid;
        knn_body<20>(x1 + (size_t)b*512, xyz4 + (size_t)b*N_, s, N_, ni1 + (size_t)b*512*20);
    } else if (blk < 6) {
        int s = (blk-4)*128 + tid;
        knn_body<20>(x2 + (size_t)b*256, x1 + (size_t)b*512, s, 512, ni2 + (size_t)b*256*20);
    } else if (blk < 7) {
        int s = tid;
        knn_body<20>(x3 + (size_t)b*128, x2 + (size_t)b*256, s, 256, ni3 + (size_t)b*128*20);
    } else {
        if (tid < 64)
            knn_body<20>(x4 + (size_t)b*64, x3 + (size_t)b*128, tid, 128, ni4 + (size_t)b*64*20);
    }
}

__global__ void knn3_all_kernel(const float4* __restrict__ xyz4,
                                const float4* __restrict__ x1, const float4* __restrict__ x2,
                                const float4* __restrict__ x3, const float4* __restrict__ x4,
                                int* __restrict__ i30, int* __restrict__ i31,
                                int* __restrict__ i32, int* __restrict__ i33) {
    int blk = blockIdx.x, b = blockIdx.y, tid = threadIdx.x;
    if (blk < 32) {
        int s = blk*128 + tid;
        knn_body<3>(xyz4 + (size_t)b*N_, x1 + (size_t)b*512, s, 512, i30 + (size_t)b*N_*3);
    } else if (blk < 36) {
        int s = (blk-32)*128 + tid;
        knn_body<3>(x1 + (size_t)b*512, x2 + (size_t)b*256, s, 256, i31 + (size_t)b*512*3);
    } else if (blk < 38) {
        int s = (blk-36)*128 + tid;
        knn_body<3>(x2 + (size_t)b*256, x3 + (size_t)b*128, s, 128, i32 + (size_t)b*256*3);
    } else {
        knn_body<3>(x3 + (size_t)b*128, x4 + (size_t)b*64, tid, 64, i33 + (size_t)b*128*3);
    }
}

// ---------------------------------------------------------------------------
// SA block (R3 proven form): gather-group -> MLP -> relu -> max over K=20.
// ---------------------------------------------------------------------------
template<int CIN, int COUT>
__global__ void sa_kernel(const float4* __restrict__ qxyz, const float4* __restrict__ rxyz,
                          const float* __restrict__ rfeat, const int* __restrict__ nidx,
                          const float* __restrict__ W, const float* __restrict__ bias,
                          int S, int M, float* __restrict__ out) {
    constexpr int K = 20;
    constexpr int CIN4 = (CIN + 3) & ~3;
    constexpr int CFEAT = CIN - 3;
    __shared__ __align__(16) float sg[K * CIN4];
    int s = blockIdx.x, b = blockIdx.y;
    const int* ni = nidx + ((size_t)b*S + s)*K;
    float4 qc = qxyz[(size_t)b*S + s];
    int tid = threadIdx.x;

    for (int e = tid; e < K*CIN; e += COUT) {
        int k = e / CIN, c = e - k*CIN;
        int n = ni[k];
        float v;
        if (c < 3) {
            float ctr = (c == 0) ? qc.x : (c == 1) ? qc.y : qc.z;
            v = ((const float*)(rxyz + (size_t)b*M + n))[c] - ctr;
        } else {
            v = rfeat[((size_t)b*M + n)*CFEAT + (c-3)];
        }
        sg[k*CIN4 + c] = v;
    }
    __syncthreads();

    int d = tid;
    float acc[K];
    float bb = bias[d];
    #pragma unroll
    for (int k = 0; k < K; k++) acc[k] = bb;

    constexpr int CF = CIN & ~3;
    for (int c = 0; c < CF; c += 4) {
        float w0 = W[(c+0)*COUT + d];
        float w1 = W[(c+1)*COUT + d];
        float w2 = W[(c+2)*COUT + d];
        float w3 = W[(c+3)*COUT + d];
        #pragma unroll
        for (int k = 0; k < K; k++) {
            float4 v = *(const float4*)&sg[k*CIN4 + c];
            acc[k] += v.x*w0 + v.y*w1 + v.z*w2 + v.w*w3;
        }
    }
    for (int c = CF; c < CIN; c++) {
        float w = W[c*COUT + d];
        #pragma unroll
        for (int k = 0; k < K; k++) acc[k] += sg[k*CIN4 + c]*w;
    }
    float m = acc[0];
    #pragma unroll
    for (int k = 1; k < K; k++) m = fmaxf(m, acc[k]);
    out[((size_t)b*S + s)*COUT + d] = fmaxf(m, 0.0f);
}

// ---------------------------------------------------------------------------
// FP block (R3 proven form): 3-NN interp -> concat skip -> MLP -> relu.
// ---------------------------------------------------------------------------
template<int CI, int CS, int COUT, int TS>
__global__ void fp_kernel(const float4* __restrict__ xq, const float4* __restrict__ xr,
                          const float* __restrict__ fr, const float* __restrict__ skip,
                          const int* __restrict__ idx3,
                          const float* __restrict__ W, const float* __restrict__ bias,
                          int Sq, int M, float* __restrict__ out) {
    constexpr int CTOT = CI + CS;
    constexpr int RS = (CTOT + 3) & ~3;
    __shared__ __align__(16) float cat[TS * RS];
    __shared__ float sw[TS][3];
    __shared__ int   si[TS][3];
    int b = blockIdx.y;
    int s0 = blockIdx.x * TS;
    int tid = threadIdx.x;

    if (tid < TS) {
        int s = s0 + tid;
        const int* ip = idx3 + ((size_t)b*Sq + s)*3;
        float4 qp = xq[(size_t)b*Sq + s];
        float wv[3]; int ii[3]; float wsum = 0.0f;
        #pragma unroll
        for (int j = 0; j < 3; j++) {
            int i = ip[j]; ii[j] = i;
            float4 r = xr[(size_t)b*M + i];
            float dx = r.x-qp.x, dy = r.y-qp.y, dz = r.z-qp.z;
            float dd = dx*dx + dy*dy + dz*dz;
            float w = 1.0f / (dd + 1e-8f);
            wv[j] = w; wsum += w;
        }
        float inv = 1.0f / wsum;
        #pragma unroll
        for (int j = 0; j < 3; j++) { sw[tid][j] = wv[j]*inv; si[tid][j] = ii[j]; }
    }
    __syncthreads();

    for (int e = tid; e < TS*CI; e += COUT) {
        int t = e / CI, c = e - t*CI;
        size_t base = (size_t)b*M;
        float v = sw[t][0]*fr[(base + si[t][0])*CI + c]
                + sw[t][1]*fr[(base + si[t][1])*CI + c]
                + sw[t][2]*fr[(base + si[t][2])*CI + c];
        cat[t*RS + c] = v;
    }
    for (int e = tid; e < TS*CS; e += COUT) {
        int t = e / CS, c = e - t*CS;
        cat[t*RS + CI + c] = skip[((size_t)b*Sq + s0 + t)*CS + c];
    }
    __syncthreads();

    int d = tid;
    float acc[TS];
    float bb = bias[d];
    #pragma unroll
    for (int t = 0; t < TS; t++) acc[t] = bb;

    constexpr int CF = CTOT & ~3;
    for (int c = 0; c < CF; c += 4) {
        float w0 = W[(c+0)*COUT + d];
        float w1 = W[(c+1)*COUT + d];
        float w2 = W[(c+2)*COUT + d];
        float w3 = W[(c+3)*COUT + d];
        #pragma unroll
        for (int t = 0; t < TS; t++) {
            float4 v = *(const float4*)&cat[t*RS + c];
            acc[t] += v.x*w0 + v.y*w1 + v.z*w2 + v.w*w3;
        }
    }
    for (int c = CF; c < CTOT; c++) {
        float w = W[c*COUT + d];
        #pragma unroll
        for (int t = 0; t < TS; t++) acc[t] += cat[t*RS + c]*w;
    }
    float* ob = out + ((size_t)b*Sq + s0)*COUT + d;
    #pragma unroll
    for (int t = 0; t < TS; t++) ob[(size_t)t*COUT] = fmaxf(acc[t], 0.0f);
}

// ---------------------------------------------------------------------------
// Seg head (R3 proven form)
// ---------------------------------------------------------------------------
__global__ void seg_kernel(const float* __restrict__ g0, const float* __restrict__ Wseg,
                           const float* __restrict__ bseg, float* __restrict__ out) {
    constexpr int TS = 16;
    __shared__ __align__(16) float sg[TS * 128];
    int b = blockIdx.y;
    int s0 = blockIdx.x * TS;
    int tid = threadIdx.x; // 64
    for (int e = tid; e < TS*128; e += 64)
        sg[e] = g0[((size_t)b*N_ + s0)*128 + e];
    __syncthreads();
    int j = tid;
    if (j < 50) {
        float acc[TS];
        #pragma unroll
        for (int t = 0; t < TS; t++) acc[t] = 0.0f;
        for (int c = 0; c < 128; c += 4) {
            float w0 = Wseg[(c+0)*50 + j];
            float w1 = Wseg[(c+1)*50 + j];
            float w2 = Wseg[(c+2)*50 + j];
            float w3 = Wseg[(c+3)*50 + j];
            #pragma unroll
            for (int t = 0; t < TS; t++) {
                float4 v = *(const float4*)&sg[t*128 + c];
                acc[t] += v.x*w0 + v.y*w1 + v.z*w2 + v.w*w3;
            }
        }
        float bb = bseg[j];
        #pragma unroll
        for (int t = 0; t < TS; t++)
            out[((size_t)b*N_ + s0 + t)*50 + j] = acc[t] + bb;
    }
}

// ---------------------------------------------------------------------------
// Transpose g0 [B,N,128] -> [B,128,N]
// ---------------------------------------------------------------------------
__global__ void transpose_kernel(const float* __restrict__ g0, float* __restrict__ out) {
    __shared__ float tile[32][33];
    int b = blockIdx.z;
    int n0 = blockIdx.x * 32, c0 = blockIdx.y * 32;
    int tx = threadIdx.x, ty = threadIdx.y;
    tile[ty][tx] = g0[((size_t)b*N_ + n0 + ty)*128 + c0 + tx];
    __syncthreads();
    out[((size_t)b*128 + c0 + ty)*N_ + n0 + tx] = tile[tx][ty];
}

// ---------------------------------------------------------------------------
extern "C" void kernel_launch(void* const* d_in, const int* in_sizes, int n_in,
                              void* d_out, int out_size) {
    const float* x      = (const float*)d_in[0];
    const float* cls    = (const float*)d_in[1];
    const float* W0 = (const float*)d_in[2];  const float* b0 = (const float*)d_in[3];
    const float* W1 = (const float*)d_in[4];  const float* b1 = (const float*)d_in[5];
    const float* W2 = (const float*)d_in[6];  const float* b2 = (const float*)d_in[7];
    const float* W3 = (const float*)d_in[8];  const float* b3 = (const float*)d_in[9];
    const float* F3 = (const float*)d_in[10]; const float* fb3 = (const float*)d_in[11];
    const float* F2 = (const float*)d_in[12]; const float* fb2 = (const float*)d_in[13];
    const float* F1 = (const float*)d_in[14]; const float* fb1 = (const float*)d_in[15];
    const float* F0 = (const float*)d_in[16]; const float* fb0 = (const float*)d_in[17];
    const float* Wseg = (const float*)d_in[18]; const float* bseg = (const float*)d_in[19];

    float* scratch = nullptr;
    cudaGetSymbolAddress((void**)&scratch, g_scratch);

    float4* xyz4 = (float4*)(scratch + OFF_XYZ4);
    float* nrm   = scratch + OFF_NRM;
    float* skip0 = scratch + OFF_SKIP0;
    float4* x1 = (float4*)(scratch + OFF_X1);
    float4* x2 = (float4*)(scratch + OFF_X2);
    float4* x3 = (float4*)(scratch + OFF_X3);
    float4* x4 = (float4*)(scratch + OFF_X4);
    float* f1 = scratch + OFF_F1;  float* f2 = scratch + OFF_F2;
    float* f3 = scratch + OFF_F3;  float* f4 = scratch + OFF_F4;
    float* g3 = scratch + OFF_G3;  float* g2 = scratch + OFF_G2;
    float* g1 = scratch + OFF_G1;  float* g0 = scratch + OFF_G0;
    int* ni1 = (int*)(scratch + OFF_NI1);
    int* ni2 = (int*)(scratch + OFF_NI2);
    int* ni3 = (int*)(scratch + OFF_NI3);
    int* ni4 = (int*)(scratch + OFF_NI4);
    int* i33 = (int*)(scratch + OFF_I33);
    int* i32 = (int*)(scratch + OFF_I32);
    int* i31 = (int*)(scratch + OFF_I31);
    int* i30 = (int*)(scratch + OFF_I30);

    float* out1 = (float*)d_out;                    // result [B,N,50]
    float* out2 = out1 + (size_t)B_ * N_ * 50;      // g0^T   [B,128,N]

    const int fps_smem = N_ * (int)sizeof(float4);  // 64 KB point cache
    cudaFuncSetAttribute(fps_all_kernel, cudaFuncAttributeMaxDynamicSharedMemorySize, fps_smem);

    prep_kernel<<<dim3(N_/256, B_), 256>>>(x, cls, xyz4, nrm, skip0);
    fps_all_kernel<<<B_, FPS_NT, fps_smem>>>(xyz4, x1, x2, x3, x4);

    knn20_all_kernel<<<dim3(8, B_), 128>>>(xyz4, x1, x2, x3, x4, ni1, ni2, ni3, ni4);
    knn3_all_kernel<<<dim3(39, B_), 128>>>(xyz4, x1, x2, x3, x4, i30, i31, i32, i33);

    // SA chain
    sa_kernel<6,64><<<dim3(512, B_), 64>>>(x1, xyz4, nrm, ni1, W0, b0, 512, N_, f1);
    sa_kernel<67,128><<<dim3(256, B_), 128>>>(x2, x1, f1, ni2, W1, b1, 256, 512, f2);
    sa_kernel<131,256><<<dim3(128, B_), 256>>>(x3, x2, f2, ni3, W2, b2, 128, 256, f3);
    sa_kernel<259,512><<<dim3(64, B_), 512>>>(x4, x3, f3, ni4, W3, b3, 64, 128, f4);

    // FP chain
    fp_kernel<512,256,512,8><<<dim3(128/8, B_), 512>>>(x3, x4, f4, f3, i33, F3, fb3, 128, 64, g3);
    fp_kernel<512,128,256,8><<<dim3(256/8, B_), 256>>>(x2, x3, g3, f2, i32, F2, fb2, 256, 128, g2);
    fp_kernel<256,64,128,8><<<dim3(512/8, B_), 128>>>(x1, x2, g2, f1, i31, F1, fb1, 512, 256, g1);
    fp_kernel<128,22,128,8><<<dim3(N_/8, B_), 128>>>(xyz4, x1, g1, skip0, i30, F0, fb0, N_, 512, g0);

    // Seg head + transposed feature output
    seg_kernel<<<dim3(N_/16, B_), 64>>>(g0, Wseg, bseg, out1);
    transpose_kernel<<<dim3(N_/32, 128/32, B_), dim3(32,32)>>>(g0, out2);
}